// round 6
// baseline (speedup 1.0000x reference)
#include <cuda_runtime.h>

// Bloch-vector rotations matching RX/RY/RZ = exp(-i t sigma/2) conjugation.
__device__ __forceinline__ void rotX(float t, float& x, float& y, float& z){
    float s, c; __sincosf(t, &s, &c);
    float ny = c*y - s*z, nz = s*y + c*z; y = ny; z = nz; (void)x;
}
__device__ __forceinline__ void rotY(float t, float& x, float& y, float& z){
    float s, c; __sincosf(t, &s, &c);
    float nx = c*x + s*z, nz = -s*x + c*z; x = nx; z = nz;
}
__device__ __forceinline__ void rotZ(float t, float& x, float& y, float& z){
    float s, c; __sincosf(t, &s, &c);
    float nx = c*x - s*y, ny = s*x + c*y; x = nx; y = ny;
}

__device__ __forceinline__ float wred(float v){
    #pragma unroll
    for (int o = 16; o; o >>= 1) v += __shfl_xor_sync(0xffffffffu, v, o);
    return v;
}

__global__ void __launch_bounds__(256)
qie_kernel(const float* __restrict__ x,      // [8,16,4,3]
           const float* __restrict__ posw,   // [16,2]
           const float* __restrict__ l1w,    // [20,3]
           const float* __restrict__ l2w,    // [16,3]
           const float* __restrict__ hw,     // [512,4]
           const float* __restrict__ hb,     // [512]
           float* __restrict__ out)          // [8,512]
{
    // M layout: [qubit][sympl pauli][block], sympl index = x | z<<1:
    //   0=I (always 1), 1=X, 2=Z, 3=Y
    __shared__ float M[20][4][4];
    __shared__ float Nv[16][3];     // Bloch rows of O_q  (X,Y,Z order)
    __shared__ float acc[7][8];     // [accumulator][warp]
    __shared__ float gsh[16];       // Gram: [0..9]=G(i<=j), [10..13]=W^T b, [14]=b.b

    const int b = blockIdx.x;
    const int t = threadIdx.x;
    const int warp = t >> 5, lane = t & 31;

    // ---- prefetch head GEMV operands (independent; hides L2 latency)
    const int k0 = t, k1 = t + 256;
    const float4 w0 = ((const float4*)hw)[k0];
    const float4 w1 = ((const float4*)hw)[k1];
    const float b0 = hb[k0], b1 = hb[k1];

    // ---- warps 0..2: per-qubit Bloch vectors + observable Bloch rows
    if (t < 80) {
        int qb = t / 20, i = t % 20;
        int p = 4*qb + i/5, j = i % 5;
        float vx = 0.f, vy = 0.f, vz = 1.f;
        if (j < 4) {
            const float* xp = x + (((size_t)b*16 + p)*4 + j)*3;
            rotX(xp[0], vx, vy, vz); rotY(xp[1], vx, vy, vz); rotZ(xp[2], vx, vy, vz);
        } else {
            rotX(posw[2*p], vx, vy, vz); rotY(posw[2*p+1], vx, vy, vz);
        }
        rotX(l1w[3*i], vx, vy, vz); rotY(l1w[3*i+1], vx, vy, vz); rotZ(l1w[3*i+2], vx, vy, vz);
        M[i][0][qb] = 1.f; M[i][1][qb] = vx; M[i][2][qb] = vz; M[i][3][qb] = vy;
    } else if (t < 96) {
        int q = t - 80;
        float sa, ca, sb, cb;
        __sincosf(l2w[3*q],   &sa, &ca);
        __sincosf(l2w[3*q+1], &sb, &cb);
        // O_q = U^dag Z U, U = RZ RY RX  ->  n = (-sin b, sin a cos b, cos a cos b)
        Nv[q][0] = -sb; Nv[q][1] = sa*cb; Nv[q][2] = ca*cb;
    } else if (t >= 96) {
        // ---- warps 3..7: Gram pieces, 3 components per warp over all 512 rows
        if (warp >= 3) {
            const int cw = warp - 3;  // 0..4
            float g0 = 0.f, g1 = 0.f, g2 = 0.f;
            #pragma unroll
            for (int j = 0; j < 16; ++j) {
                const int r = lane + 32*j;
                const float4 w = ((const float4*)hw)[r];
                const float bv = hb[r];
                float p0, p1, p2;
                switch (cw) {
                    case 0:  p0 = w.x*w.x; p1 = w.x*w.y; p2 = w.x*w.z; break;
                    case 1:  p0 = w.x*w.w; p1 = w.y*w.y; p2 = w.y*w.z; break;
                    case 2:  p0 = w.y*w.w; p1 = w.z*w.z; p2 = w.z*w.w; break;
                    case 3:  p0 = w.w*w.w; p1 = w.x*bv;  p2 = w.y*bv;  break;
                    default: p0 = w.z*bv;  p1 = w.w*bv;  p2 = bv*bv;   break;
                }
                g0 += p0; g1 += p1; g2 += p2;
            }
            g0 = wred(g0); g1 = wred(g1); g2 = wred(g2);
            if (lane == 0) {
                gsh[cw*3 + 0] = g0; gsh[cw*3 + 1] = g1; gsh[cw*3 + 2] = g2;
            }
        }
    }

    // ---- closed-form Clifford pullback through the 20-CNOT ring.
    // Initial Pauli digits a_j (0=I,1=X,2=Y,3=Z) on qubits 0..3 = base-4 of t.
    const int a0 = t & 3, a1 = (t >> 2) & 3, a2 = (t >> 4) & 3, a3 = (t >> 6) & 3;
    const int x0 = (a0 ^ (a0 >> 1)) & 1, z0 = (a0 >> 1) & 1;
    const int x1 = (a1 ^ (a1 >> 1)) & 1, z1 = (a1 >> 1) & 1;
    const int x2 = (a2 ^ (a2 >> 1)) & 1, z2 = (a2 >> 1) & 1;
    const int x3 = (a3 ^ (a3 >> 1)) & 1, z3 = (a3 >> 1) & 1;
    const int p0 =  x0       | ((z1 ^ z2 ^ z3)      << 1);
    const int p1 = (x0 ^ x1) | ((z0 ^ z1 ^ z2 ^ z3) << 1);
    const int p2 = (x1 ^ x2) | ((z0 ^ z2 ^ z3)      << 1);
    const int p3 = (x2 ^ x3) | ((z0 ^ z3)           << 1);
    const int p4 =  x3       | ( z0                 << 1);
    const int S1 = z0 ^ z1 ^ z2 ^ z3, S2 = z0 ^ z2 ^ z3, S3 = z0 ^ z3, S4 = z0;
    const int sign = (x0 & S1 & (1 ^ x1 ^ z0)) ^ (x1 & S2 & (1 ^ x2 ^ z1))
                   ^ (x2 & S3 & (1 ^ x3 ^ z2)) ^ (x3 & S4 & (1 ^ z3));
    const float sgn = 1.f - 2.f * (float)sign;

    __syncthreads();   // barrier 1: M, Nv, gsh ready

    // ---- suffix product SZ[qb] = prod_{i=5..19} M[i][Z][qb]  (tree, fixed addrs)
    float4 f[15];
    #pragma unroll
    for (int i = 0; i < 15; ++i) f[i] = *(const float4*)&M[5 + i][2][0];
    #pragma unroll
    for (int s = 1; s < 16; s <<= 1)
        #pragma unroll
        for (int i = 0; i + s < 15; i += 2*s) {
            f[i].x *= f[i+s].x; f[i].y *= f[i+s].y;
            f[i].z *= f[i+s].z; f[i].w *= f[i+s].w;
        }

    // ---- pattern product over qubits 0..4 (tree)
    float4 m0 = *(const float4*)&M[0][p0][0];
    float4 m1 = *(const float4*)&M[1][p1][0];
    float4 m2 = *(const float4*)&M[2][p2][0];
    float4 m3 = *(const float4*)&M[3][p3][0];
    float4 m4 = *(const float4*)&M[4][p4][0];
    float v0 = (m0.x*m1.x) * (m2.x*m3.x) * m4.x;
    float v1 = (m0.y*m1.y) * (m2.y*m3.y) * m4.y;
    float v2 = (m0.z*m1.z) * (m2.z*m3.z) * m4.z;
    float v3 = (m0.w*m1.w) * (m2.w*m3.w) * m4.w;
    if (z0) { v0 *= f[0].x; v1 *= f[0].y; v2 *= f[0].z; v3 *= f[0].w; }
    v0 *= sgn; v1 *= sgn; v2 *= sgn; v3 *= sgn;

    // ---- 7 expectations: [0..3] Efull[qb]; [4] e123; [5] e01; [6] e012
    float part[7] = {0,0,0,0,0,0,0};
    const bool f0n = a0 > 0, f1n = a1 > 0, f2n = a2 > 0, f3n = a3 > 0;
    if (f0n && f1n && f2n && f3n) {
        part[0] = Nv[0][a0-1]  * Nv[1][a1-1]  * Nv[2][a2-1]  * Nv[3][a3-1]  * v0;
        part[1] = Nv[4][a0-1]  * Nv[5][a1-1]  * Nv[6][a2-1]  * Nv[7][a3-1]  * v1;
        part[2] = Nv[8][a0-1]  * Nv[9][a1-1]  * Nv[10][a2-1] * Nv[11][a3-1] * v2;
        part[3] = Nv[12][a0-1] * Nv[13][a1-1] * Nv[14][a2-1] * Nv[15][a3-1] * v3;
    }
    if (!f0n && f1n && f2n && f3n)
        part[4] = Nv[1][a1-1] * Nv[2][a2-1] * Nv[3][a3-1] * v0;
    if (f0n && f1n && !f2n && !f3n)
        part[5] = Nv[0][a0-1] * Nv[1][a1-1] * v0;
    if (f0n && f1n && f2n && !f3n)
        part[6] = Nv[0][a0-1] * Nv[1][a1-1] * Nv[2][a2-1] * v0;

    #pragma unroll
    for (int k = 0; k < 7; ++k) {
        float r = wred(part[k]);
        if (lane == 0) acc[k][warp] = r;
    }

    // Gram sums (ready since barrier 1; off the critical path)
    float G[16];
    {
        float4 ga = *(const float4*)&gsh[0];
        float4 gb = *(const float4*)&gsh[4];
        float4 gc = *(const float4*)&gsh[8];
        float4 gd = *(const float4*)&gsh[12];
        G[0]=ga.x; G[1]=ga.y; G[2]=ga.z; G[3]=ga.w;
        G[4]=gb.x; G[5]=gb.y; G[6]=gb.z; G[7]=gb.w;
        G[8]=gc.x; G[9]=gc.y; G[10]=gc.z; G[11]=gc.w;
        G[12]=gd.x; G[13]=gd.y; G[14]=gd.z;
    }

    __syncthreads();   // barrier 2: acc ready

    // ---- final combine (all threads, fixed order, float4 loads)
    float E[7];
    #pragma unroll
    for (int k = 0; k < 7; ++k) {
        float4 alo = *(const float4*)&acc[k][0];
        float4 ahi = *(const float4*)&acc[k][4];
        E[k] = ((alo.x + alo.y) + (alo.z + alo.w)) + ((ahi.x + ahi.y) + (ahi.z + ahi.w));
    }
    const float q0 = E[4] * E[1] * E[2] * E[3];  // e0
    const float q1 = E[5];                       // e1
    const float q2 = E[6];                       // e2
    const float q3 = E[0];                       // e3

    // ---- head: y = q @ W^T + b ; norm via Gram: n = q^T G q + 2 c.q + b.b
    float y0 = b0 + q0*w0.x + q1*w0.y + q2*w0.z + q3*w0.w;
    float y1 = b1 + q0*w1.x + q1*w1.y + q2*w1.z + q3*w1.w;
    float n = G[14]
            + G[0]*q0*q0 + G[4]*q1*q1 + G[7]*q2*q2 + G[9]*q3*q3
            + 2.f*(G[1]*q0*q1 + G[2]*q0*q2 + G[3]*q0*q3
                 + G[5]*q1*q2 + G[6]*q1*q3 + G[8]*q2*q3
                 + G[10]*q0 + G[11]*q1 + G[12]*q2 + G[13]*q3);
    const float d = fmaxf(sqrtf(n), 1e-12f);
    const float r = 1.0f / d;
    out[(size_t)b*512 + k0] = y0 * r;
    out[(size_t)b*512 + k1] = y1 * r;
}

extern "C" void kernel_launch(void* const* d_in, const int* in_sizes, int n_in,
                              void* d_out, int out_size)
{
    // Map inputs by unique element counts:
    // x=1536, pos_weights=32, layer_1_weights=60, layer_2_weights=48,
    // head_w=2048, head_b=512
    const float *x = nullptr, *pw = nullptr, *l1 = nullptr,
                *l2 = nullptr, *hw = nullptr, *hb = nullptr;
    for (int i = 0; i < n_in; ++i) {
        const float* p = (const float*)d_in[i];
        switch (in_sizes[i]) {
            case 1536: x  = p; break;
            case 32:   pw = p; break;
            case 60:   l1 = p; break;
            case 48:   l2 = p; break;
            case 2048: hw = p; break;
            case 512:  hb = p; break;
            default: break;
        }
    }
    qie_kernel<<<8, 256>>>(x, pw, l1, l2, hw, hb, (float*)d_out);
}

// round 7
// speedup vs baseline: 1.1627x; 1.1627x over previous
#include <cuda_runtime.h>

// Bloch-vector rotations matching RX/RY/RZ = exp(-i t sigma/2) conjugation.
__device__ __forceinline__ void rotX(float t, float& x, float& y, float& z){
    float s, c; __sincosf(t, &s, &c);
    float ny = c*y - s*z, nz = s*y + c*z; y = ny; z = nz; (void)x;
}
__device__ __forceinline__ void rotY(float t, float& x, float& y, float& z){
    float s, c; __sincosf(t, &s, &c);
    float nx = c*x + s*z, nz = -s*x + c*z; x = nx; z = nz;
}
__device__ __forceinline__ void rotZ(float t, float& x, float& y, float& z){
    float s, c; __sincosf(t, &s, &c);
    float nx = c*x - s*y, ny = s*x + c*y; x = nx; y = ny;
}

__device__ __forceinline__ float wred(float v){
    #pragma unroll
    for (int o = 16; o; o >>= 1) v += __shfl_xor_sync(0xffffffffu, v, o);
    return v;
}

__global__ void __launch_bounds__(256)
qie_kernel(const float* __restrict__ x,      // [8,16,4,3]
           const float* __restrict__ posw,   // [16,2]
           const float* __restrict__ l1w,    // [20,3]
           const float* __restrict__ l2w,    // [16,3]
           const float* __restrict__ hw,     // [512,4]
           const float* __restrict__ hb,     // [512]
           float* __restrict__ out)          // [8,512]
{
    // M layout: [qubit][sympl pauli][block], sympl index = x | z<<1:
    //   0=I (always 1), 1=X, 2=Z, 3=Y
    __shared__ float M[20][4][4];
    __shared__ float Nv[16][3];     // Bloch rows of O_q  (X,Y,Z order)
    __shared__ float acc[7][8];     // [accumulator][warp]
    __shared__ float nwarp[8];

    const int b = blockIdx.x;
    const int t = threadIdx.x;
    const int warp = t >> 5, lane = t & 31;

    // ---- prefetch head GEMV operands (independent; hides L2 latency)
    const int k0 = t, k1 = t + 256;
    const float4 w0 = ((const float4*)hw)[k0];
    const float4 w1 = ((const float4*)hw)[k1];
    const float b0 = hb[k0], b1 = hb[k1];

    // ---- warps 0..2: per-qubit Bloch vectors + observable Bloch rows
    if (t < 80) {
        int qb = t / 20, i = t % 20;
        int p = 4*qb + i/5, j = i % 5;
        float vx = 0.f, vy = 0.f, vz = 1.f;
        if (j < 4) {
            const float* xp = x + (((size_t)b*16 + p)*4 + j)*3;
            rotX(xp[0], vx, vy, vz); rotY(xp[1], vx, vy, vz); rotZ(xp[2], vx, vy, vz);
        } else {
            rotX(posw[2*p], vx, vy, vz); rotY(posw[2*p+1], vx, vy, vz);
        }
        rotX(l1w[3*i], vx, vy, vz); rotY(l1w[3*i+1], vx, vy, vz); rotZ(l1w[3*i+2], vx, vy, vz);
        M[i][0][qb] = 1.f; M[i][1][qb] = vx; M[i][2][qb] = vz; M[i][3][qb] = vy;
    } else if (t < 96) {
        int q = t - 80;
        float sa, ca, sb, cb;
        __sincosf(l2w[3*q],   &sa, &ca);
        __sincosf(l2w[3*q+1], &sb, &cb);
        // O_q = U^dag Z U, U = RZ RY RX  ->  n = (-sin b, sin a cos b, cos a cos b)
        Nv[q][0] = -sb; Nv[q][1] = sa*cb; Nv[q][2] = ca*cb;
    }

    // ---- closed-form Clifford pullback through the 20-CNOT ring (pure ALU, ~20 ops).
    // Initial Pauli digits a_j (0=I,1=X,2=Y,3=Z) on qubits 0..3 = base-4 of t.
    const int a0 = t & 3, a1 = (t >> 2) & 3, a2 = (t >> 4) & 3, a3 = (t >> 6) & 3;
    const int x0 = (a0 ^ (a0 >> 1)) & 1, z0 = (a0 >> 1) & 1;
    const int x1 = (a1 ^ (a1 >> 1)) & 1, z1 = (a1 >> 1) & 1;
    const int x2 = (a2 ^ (a2 >> 1)) & 1, z2 = (a2 >> 1) & 1;
    const int x3 = (a3 ^ (a3 >> 1)) & 1, z3 = (a3 >> 1) & 1;
    const int p0 =  x0       | ((z1 ^ z2 ^ z3)      << 1);
    const int p1 = (x0 ^ x1) | ((z0 ^ z1 ^ z2 ^ z3) << 1);
    const int p2 = (x1 ^ x2) | ((z0 ^ z2 ^ z3)      << 1);
    const int p3 = (x2 ^ x3) | ((z0 ^ z3)           << 1);
    const int p4 =  x3       | ( z0                 << 1);
    const int S1 = z0 ^ z1 ^ z2 ^ z3, S2 = z0 ^ z2 ^ z3, S3 = z0 ^ z3, S4 = z0;
    const int sign = (x0 & S1 & (1 ^ x1 ^ z0)) ^ (x1 & S2 & (1 ^ x2 ^ z1))
                   ^ (x2 & S3 & (1 ^ x3 ^ z2)) ^ (x3 & S4 & (1 ^ z3));
    const float sgn = 1.f - 2.f * (float)sign;

    __syncthreads();   // barrier 1: M, Nv ready

    // ---- <psi_qb | P | psi_qb> for all 4 blocks: one LDS.128 per qubit.
    // Qubits 5..19 share the uniform index z0<<1 (index 0 rows are 1.0f).
    float v0 = sgn, v1 = sgn, v2 = sgn, v3 = sgn;
    {
        float4 f;
        f = *(const float4*)&M[0][p0][0]; v0 *= f.x; v1 *= f.y; v2 *= f.z; v3 *= f.w;
        f = *(const float4*)&M[1][p1][0]; v0 *= f.x; v1 *= f.y; v2 *= f.z; v3 *= f.w;
        f = *(const float4*)&M[2][p2][0]; v0 *= f.x; v1 *= f.y; v2 *= f.z; v3 *= f.w;
        f = *(const float4*)&M[3][p3][0]; v0 *= f.x; v1 *= f.y; v2 *= f.z; v3 *= f.w;
        f = *(const float4*)&M[4][p4][0]; v0 *= f.x; v1 *= f.y; v2 *= f.z; v3 *= f.w;
        const int iz = z0 << 1;
        #pragma unroll
        for (int i = 5; i < 20; ++i) {
            f = *(const float4*)&M[i][iz][0];
            v0 *= f.x; v1 *= f.y; v2 *= f.z; v3 *= f.w;
        }
    }

    // ---- 7 expectations: [0..3] Efull[qb]; [4] e123; [5] e01; [6] e012
    float part[7] = {0,0,0,0,0,0,0};
    const bool f0n = a0 > 0, f1n = a1 > 0, f2n = a2 > 0, f3n = a3 > 0;
    if (f0n && f1n && f2n && f3n) {
        part[0] = Nv[0][a0-1]  * Nv[1][a1-1]  * Nv[2][a2-1]  * Nv[3][a3-1]  * v0;
        part[1] = Nv[4][a0-1]  * Nv[5][a1-1]  * Nv[6][a2-1]  * Nv[7][a3-1]  * v1;
        part[2] = Nv[8][a0-1]  * Nv[9][a1-1]  * Nv[10][a2-1] * Nv[11][a3-1] * v2;
        part[3] = Nv[12][a0-1] * Nv[13][a1-1] * Nv[14][a2-1] * Nv[15][a3-1] * v3;
    }
    if (!f0n && f1n && f2n && f3n)
        part[4] = Nv[1][a1-1] * Nv[2][a2-1] * Nv[3][a3-1] * v0;
    if (f0n && f1n && !f2n && !f3n)
        part[5] = Nv[0][a0-1] * Nv[1][a1-1] * v0;
    if (f0n && f1n && f2n && !f3n)
        part[6] = Nv[0][a0-1] * Nv[1][a1-1] * Nv[2][a2-1] * v0;

    #pragma unroll
    for (int k = 0; k < 7; ++k) {
        float r = wred(part[k]);
        if (lane == 0) acc[k][warp] = r;
    }
    __syncthreads();   // barrier 2: acc ready

    // ---- final combine (all threads, fixed order, float4 loads)
    float E[7];
    #pragma unroll
    for (int k = 0; k < 7; ++k) {
        float4 alo = *(const float4*)&acc[k][0];
        float4 ahi = *(const float4*)&acc[k][4];
        E[k] = ((alo.x + alo.y) + (alo.z + alo.w)) + ((ahi.x + ahi.y) + (ahi.z + ahi.w));
    }
    const float q0 = E[4] * E[1] * E[2] * E[3];  // e0
    const float q1 = E[5];                       // e1
    const float q2 = E[6];                       // e2
    const float q3 = E[0];                       // e3

    // ---- head: y = q @ W^T + b, then L2 normalize; 2 outputs per thread
    float y0 = b0 + q0*w0.x + q1*w0.y + q2*w0.z + q3*w0.w;
    float y1 = b1 + q0*w1.x + q1*w1.y + q2*w1.z + q3*w1.w;
    float ssum = wred(y0*y0 + y1*y1);
    if (lane == 0) nwarp[warp] = ssum;
    __syncthreads();   // barrier 3: nwarp ready

    float4 nlo = *(const float4*)&nwarp[0];
    float4 nhi = *(const float4*)&nwarp[4];
    const float n = ((nlo.x + nlo.y) + (nlo.z + nlo.w)) + ((nhi.x + nhi.y) + (nhi.z + nhi.w));
    const float d = fmaxf(sqrtf(n), 1e-12f);
    const float r = 1.0f / d;
    out[(size_t)b*512 + k0] = y0 * r;
    out[(size_t)b*512 + k1] = y1 * r;
}

extern "C" void kernel_launch(void* const* d_in, const int* in_sizes, int n_in,
                              void* d_out, int out_size)
{
    // Map inputs by unique element counts:
    // x=1536, pos_weights=32, layer_1_weights=60, layer_2_weights=48,
    // head_w=2048, head_b=512
    const float *x = nullptr, *pw = nullptr, *l1 = nullptr,
                *l2 = nullptr, *hw = nullptr, *hb = nullptr;
    for (int i = 0; i < n_in; ++i) {
        const float* p = (const float*)d_in[i];
        switch (in_sizes[i]) {
            case 1536: x  = p; break;
            case 32:   pw = p; break;
            case 60:   l1 = p; break;
            case 48:   l2 = p; break;
            case 2048: hw = p; break;
            case 512:  hb = p; break;
            default: break;
        }
    }
    qie_kernel<<<8, 256>>>(x, pw, l1, l2, hw, hb, (float*)d_out);
}

// round 8
// speedup vs baseline: 1.2335x; 1.0609x over previous
#include <cuda_runtime.h>
#include <cstdint>

__device__ __forceinline__ float wred(float v){
    #pragma unroll
    for (int o = 16; o; o >>= 1) v += __shfl_xor_sync(0xffffffffu, v, o);
    return v;
}

// packed f32x2 multiply: a.lo*=v.lo, a.hi*=v.hi  (sm_100 family)
__device__ __forceinline__ void mul2(unsigned long long& a, unsigned long long v){
    asm("mul.rn.f32x2 %0, %0, %1;" : "+l"(a) : "l"(v));
}
__device__ __forceinline__ void lds_v2u64(unsigned long long& lo, unsigned long long& hi, uint32_t addr){
    asm volatile("ld.shared.v2.u64 {%0,%1}, [%2];" : "=l"(lo), "=l"(hi) : "r"(addr));
}
__device__ __forceinline__ unsigned long long packf2(float x, float y){
    unsigned long long r;
    asm("mov.b64 %0, {%1,%2};" : "=l"(r) : "f"(x), "f"(y));
    return r;
}
__device__ __forceinline__ void unpackf2(float& x, float& y, unsigned long long v){
    asm("mov.b64 {%0,%1}, %2;" : "=f"(x), "=f"(y) : "l"(v));
}

__global__ void __launch_bounds__(256)
qie_kernel(const float* __restrict__ x,      // [8,16,4,3]
           const float* __restrict__ posw,   // [16,2]
           const float* __restrict__ l1w,    // [20,3]
           const float* __restrict__ l2w,    // [16,3]
           const float* __restrict__ hw,     // [512,4]
           const float* __restrict__ hb,     // [512]
           float* __restrict__ out)          // [8,512]
{
    // M layout: [qubit][sympl pauli][block], sympl index = x | z<<1:
    //   0=I (always 1), 1=X, 2=Z, 3=Y
    __shared__ __align__(16) float M[20][4][4];
    __shared__ float Nv[16][3];     // Bloch rows of O_q  (X,Y,Z order)
    __shared__ __align__(16) float acc[7][8];   // [accumulator][warp]
    __shared__ __align__(16) float nwarp[8];

    const int b = blockIdx.x;
    const int t = threadIdx.x;
    const int warp = t >> 5, lane = t & 31;

    // ---- warps 0..2 (threads 0..79): per-qubit Bloch vectors.
    //      warp 3 lanes 0..15 (threads 96..111): observable Bloch rows.
    //      (Nv moved off warp 2 to kill intra-warp path serialization.)
    if (t < 80) {
        const int qb = t / 20, i = t % 20;
        const int p = 4*qb + i/5, j = i % 5;
        // load all angles first (critical-path LDGs go before anything else)
        float A0, A1, A2;
        if (j < 4) {
            const float* xp = x + (((size_t)b*16 + p)*4 + j)*3;
            A0 = xp[0]; A1 = xp[1]; A2 = xp[2];
        } else {
            A0 = posw[2*p]; A1 = posw[2*p+1]; A2 = 0.f;   // rz(0)=I
        }
        const float B0 = l1w[3*i], B1 = l1w[3*i+1], B2 = l1w[3*i+2];
        // all 6 sincos issue back-to-back (no dependences)
        float s0,c0,s1,c1,s2,c2, t0,d0,t1,d1,t2,d2;
        __sincosf(A0,&s0,&c0); __sincosf(A1,&s1,&c1); __sincosf(A2,&s2,&c2);
        __sincosf(B0,&t0,&d0); __sincosf(B1,&t1,&d1); __sincosf(B2,&t2,&d2);
        // v = Rz(A2)Ry(A1)Rx(A0) e_z  (closed form, shallow)
        float vx = s1*c0, vy = -s0, vz = c1*c0;
        float nx = c2*vx - s2*vy, ny = s2*vx + c2*vy;       // Rz(A2)
        vx = nx; vy = ny;
        // layer-1: Rx(B0), Ry(B1), Rz(B2)
        ny = d0*vy - t0*vz;  vz = t0*vy + d0*vz;  vy = ny;  // Rx
        nx = d1*vx + t1*vz;  vz = -t1*vx + d1*vz; vx = nx;  // Ry
        nx = d2*vx - t2*vy;  ny = t2*vx + d2*vy;  vx = nx; vy = ny; // Rz
        M[i][0][qb] = 1.f; M[i][1][qb] = vx; M[i][2][qb] = vz; M[i][3][qb] = vy;
    } else if (t >= 96 && t < 112) {
        const int q = t - 96;
        float sa, ca, sb, cb;
        __sincosf(l2w[3*q],   &sa, &ca);
        __sincosf(l2w[3*q+1], &sb, &cb);
        // O_q = U^dag Z U, U = RZ RY RX  ->  n = (-sin b, sin a cos b, cos a cos b)
        Nv[q][0] = -sb; Nv[q][1] = sa*cb; Nv[q][2] = ca*cb;
    }

    // ---- prefetch head GEMV operands AFTER prologue issue (used post-barrier-2)
    const int k0 = t, k1 = t + 256;
    const float4 w0 = ((const float4*)hw)[k0];
    const float4 w1 = ((const float4*)hw)[k1];
    const float b0 = hb[k0], b1 = hb[k1];

    // ---- closed-form Clifford pullback through the 20-CNOT ring (pure ALU).
    const int a0 = t & 3, a1 = (t >> 2) & 3, a2 = (t >> 4) & 3, a3 = (t >> 6) & 3;
    const int x0 = (a0 ^ (a0 >> 1)) & 1, z0 = (a0 >> 1) & 1;
    const int x1 = (a1 ^ (a1 >> 1)) & 1, z1 = (a1 >> 1) & 1;
    const int x2 = (a2 ^ (a2 >> 1)) & 1, z2 = (a2 >> 1) & 1;
    const int x3 = (a3 ^ (a3 >> 1)) & 1, z3 = (a3 >> 1) & 1;
    const int p0 =  x0       | ((z1 ^ z2 ^ z3)      << 1);
    const int p1 = (x0 ^ x1) | ((z0 ^ z1 ^ z2 ^ z3) << 1);
    const int p2 = (x1 ^ x2) | ((z0 ^ z2 ^ z3)      << 1);
    const int p3 = (x2 ^ x3) | ((z0 ^ z3)           << 1);
    const int p4 =  x3       | ( z0                 << 1);
    const int S1 = z0 ^ z1 ^ z2 ^ z3, S2 = z0 ^ z2 ^ z3, S3 = z0 ^ z3, S4 = z0;
    const int sign = (x0 & S1 & (1 ^ x1 ^ z0)) ^ (x1 & S2 & (1 ^ x2 ^ z1))
                   ^ (x2 & S3 & (1 ^ x3 ^ z2)) ^ (x3 & S4 & (1 ^ z3));
    const float sgn = 1.f - 2.f * (float)sign;

    __syncthreads();   // barrier 1: M, Nv ready

    // ---- <psi_qb | P | psi_qb> for all 4 blocks.
    // Packed f32x2: each M row = 16B; two 64-bit halves = (blk0,blk1),(blk2,blk3).
    // Even/odd accumulator split halves the multiply-chain depth.
    float v0, v1, v2, v3;
    {
        const uint32_t mb = (uint32_t)__cvta_generic_to_shared(M);
        const int iz = z0 << 1;
        uint32_t ad[20];
        ad[0] = mb + (0*4 + p0)*16; ad[1] = mb + (1*4 + p1)*16;
        ad[2] = mb + (2*4 + p2)*16; ad[3] = mb + (3*4 + p3)*16;
        ad[4] = mb + (4*4 + p4)*16;
        #pragma unroll
        for (int i = 5; i < 20; ++i) ad[i] = mb + (i*4 + iz)*16;

        unsigned long long aE01, aE23, aO01, aO23;
        // init: even acc with qubit 0, odd acc with qubit 1
        lds_v2u64(aE01, aE23, ad[0]);
        lds_v2u64(aO01, aO23, ad[1]);
        #pragma unroll
        for (int i = 2; i < 20; i += 2) {
            unsigned long long lo, hi;
            lds_v2u64(lo, hi, ad[i]);
            mul2(aE01, lo); mul2(aE23, hi);
            lds_v2u64(lo, hi, ad[i+1]);
            mul2(aO01, lo); mul2(aO23, hi);
        }
        mul2(aE01, aO01); mul2(aE23, aO23);
        unpackf2(v0, v1, aE01);
        unpackf2(v2, v3, aE23);
        v0 *= sgn; v1 *= sgn; v2 *= sgn; v3 *= sgn;
    }

    // ---- 7 expectations: [0..3] Efull[qb]; [4] e123; [5] e01; [6] e012
    float part[7] = {0,0,0,0,0,0,0};
    const bool f0n = a0 > 0, f1n = a1 > 0, f2n = a2 > 0, f3n = a3 > 0;
    if (f0n && f1n && f2n && f3n) {
        part[0] = Nv[0][a0-1]  * Nv[1][a1-1]  * Nv[2][a2-1]  * Nv[3][a3-1]  * v0;
        part[1] = Nv[4][a0-1]  * Nv[5][a1-1]  * Nv[6][a2-1]  * Nv[7][a3-1]  * v1;
        part[2] = Nv[8][a0-1]  * Nv[9][a1-1]  * Nv[10][a2-1] * Nv[11][a3-1] * v2;
        part[3] = Nv[12][a0-1] * Nv[13][a1-1] * Nv[14][a2-1] * Nv[15][a3-1] * v3;
    }
    if (!f0n && f1n && f2n && f3n)
        part[4] = Nv[1][a1-1] * Nv[2][a2-1] * Nv[3][a3-1] * v0;
    if (f0n && f1n && !f2n && !f3n)
        part[5] = Nv[0][a0-1] * Nv[1][a1-1] * v0;
    if (f0n && f1n && f2n && !f3n)
        part[6] = Nv[0][a0-1] * Nv[1][a1-1] * Nv[2][a2-1] * v0;

    #pragma unroll
    for (int k = 0; k < 7; ++k) {
        float r = wred(part[k]);
        if (lane == 0) acc[k][warp] = r;
    }
    __syncthreads();   // barrier 2: acc ready

    // ---- final combine (all threads, fixed order, float4 loads)
    float E[7];
    #pragma unroll
    for (int k = 0; k < 7; ++k) {
        float4 alo = *(const float4*)&acc[k][0];
        float4 ahi = *(const float4*)&acc[k][4];
        E[k] = ((alo.x + alo.y) + (alo.z + alo.w)) + ((ahi.x + ahi.y) + (ahi.z + ahi.w));
    }
    const float q0 = E[4] * E[1] * E[2] * E[3];  // e0
    const float q1 = E[5];                       // e1
    const float q2 = E[6];                       // e2
    const float q3 = E[0];                       // e3

    // ---- head: y = q @ W^T + b, then L2 normalize; 2 outputs per thread
    float y0 = b0 + q0*w0.x + q1*w0.y + q2*w0.z + q3*w0.w;
    float y1 = b1 + q0*w1.x + q1*w1.y + q2*w1.z + q3*w1.w;
    float ssum = wred(y0*y0 + y1*y1);
    if (lane == 0) nwarp[warp] = ssum;
    __syncthreads();   // barrier 3: nwarp ready

    float4 nlo = *(const float4*)&nwarp[0];
    float4 nhi = *(const float4*)&nwarp[4];
    const float n = ((nlo.x + nlo.y) + (nlo.z + nlo.w)) + ((nhi.x + nhi.y) + (nhi.z + nhi.w));
    const float d = fmaxf(sqrtf(n), 1e-12f);
    const float r = 1.0f / d;
    out[(size_t)b*512 + k0] = y0 * r;
    out[(size_t)b*512 + k1] = y1 * r;
}

extern "C" void kernel_launch(void* const* d_in, const int* in_sizes, int n_in,
                              void* d_out, int out_size)
{
    // Map inputs by unique element counts:
    // x=1536, pos_weights=32, layer_1_weights=60, layer_2_weights=48,
    // head_w=2048, head_b=512
    const float *x = nullptr, *pw = nullptr, *l1 = nullptr,
                *l2 = nullptr, *hw = nullptr, *hb = nullptr;
    for (int i = 0; i < n_in; ++i) {
        const float* p = (const float*)d_in[i];
        switch (in_sizes[i]) {
            case 1536: x  = p; break;
            case 32:   pw = p; break;
            case 60:   l1 = p; break;
            case 48:   l2 = p; break;
            case 2048: hw = p; break;
            case 512:  hb = p; break;
            default: break;
        }
    }
    qie_kernel<<<8, 256>>>(x, pw, l1, l2, hw, hb, (float*)d_out);
}